// round 1
// baseline (speedup 1.0000x reference)
#include <cuda_runtime.h>
#include <cuda_bf16.h>
#include <math.h>

// Problem constants
#define BATCH 2
#define SEQ   2048
#define EMB   1024
#define HEADS 16
#define HDIM  64
#define MROWS (BATCH * SEQ)   // 4096

// ---------------- scratch (device globals; no allocations allowed) ---------
__device__ float g_Q[MROWS * EMB];
__device__ float g_K[MROWS * EMB];
__device__ float g_V[MROWS * EMB];
__device__ float g_C[MROWS * EMB];

// ============================================================================
// SGEMM: C[M,N] = A[M,K] @ W[K,N] + bias[N]
// BM=BN=128, BK=16, 256 threads, 8x8 per thread.
// ============================================================================
#define BM 128
#define BN 128
#define BK 16
#define ASTR (BM + 4)   // padded stride for transposed A tile

__global__ void __launch_bounds__(256)
gemm_bias_kernel(const float* __restrict__ A, const float* __restrict__ W,
                 const float* __restrict__ bias, float* __restrict__ C,
                 int M, int N, int K)
{
    __shared__ float As[BK][ASTR];   // As[k][m]
    __shared__ float Bs[BK][BN];     // Bs[k][n]

    const int tid = threadIdx.x;
    const int bm = blockIdx.y * BM;
    const int bn = blockIdx.x * BN;
    const int tx = tid & 15;        // col group
    const int ty = tid >> 4;        // row group

    // load indices
    const int arow = tid >> 2;           // 0..63
    const int acol = (tid & 3) * 4;      // 0,4,8,12
    const int brow = tid >> 5;           // 0..7
    const int bcol = (tid & 31) * 4;     // 0..124

    float acc[8][8];
#pragma unroll
    for (int i = 0; i < 8; ++i)
#pragma unroll
        for (int j = 0; j < 8; ++j) acc[i][j] = 0.f;

    for (int k0 = 0; k0 < K; k0 += BK) {
        // A tile 128x16 -> transposed store
#pragma unroll
        for (int p = 0; p < 2; ++p) {
            int r = arow + p * 64;
            float4 v = *(const float4*)&A[(size_t)(bm + r) * K + k0 + acol];
            As[acol + 0][r] = v.x;
            As[acol + 1][r] = v.y;
            As[acol + 2][r] = v.z;
            As[acol + 3][r] = v.w;
        }
        // B tile 16x128
#pragma unroll
        for (int p = 0; p < 2; ++p) {
            int r = brow + p * 8;
            *(float4*)&Bs[r][bcol] = *(const float4*)&W[(size_t)(k0 + r) * N + bn + bcol];
        }
        __syncthreads();

#pragma unroll
        for (int k = 0; k < BK; ++k) {
            float a[8], b[8];
            float4 a0 = *(const float4*)&As[k][ty * 8];
            float4 a1 = *(const float4*)&As[k][ty * 8 + 4];
            float4 b0 = *(const float4*)&Bs[k][tx * 8];
            float4 b1 = *(const float4*)&Bs[k][tx * 8 + 4];
            a[0] = a0.x; a[1] = a0.y; a[2] = a0.z; a[3] = a0.w;
            a[4] = a1.x; a[5] = a1.y; a[6] = a1.z; a[7] = a1.w;
            b[0] = b0.x; b[1] = b0.y; b[2] = b0.z; b[3] = b0.w;
            b[4] = b1.x; b[5] = b1.y; b[6] = b1.z; b[7] = b1.w;
#pragma unroll
            for (int i = 0; i < 8; ++i)
#pragma unroll
                for (int j = 0; j < 8; ++j)
                    acc[i][j] = fmaf(a[i], b[j], acc[i][j]);
        }
        __syncthreads();
    }

    // epilogue with bias
    float bj[8];
#pragma unroll
    for (int j = 0; j < 8; ++j) bj[j] = bias[bn + tx * 8 + j];

#pragma unroll
    for (int i = 0; i < 8; ++i) {
        size_t row = (size_t)(bm + ty * 8 + i);
        float4 o0, o1;
        o0.x = acc[i][0] + bj[0]; o0.y = acc[i][1] + bj[1];
        o0.z = acc[i][2] + bj[2]; o0.w = acc[i][3] + bj[3];
        o1.x = acc[i][4] + bj[4]; o1.y = acc[i][5] + bj[5];
        o1.z = acc[i][6] + bj[6]; o1.w = acc[i][7] + bj[7];
        *(float4*)&C[row * N + bn + tx * 8]     = o0;
        *(float4*)&C[row * N + bn + tx * 8 + 4] = o1;
    }
}

// ============================================================================
// Flash attention: per (b,h,q-tile of 64) block. 256 threads.
// Qs/Ks transposed [d][s] for vectorized fragment loads; Vs natural [s][d].
// Online softmax with running (m, l).
// ============================================================================
#define AS 68   // smem stride

__global__ void __launch_bounds__(256)
attn_kernel(const float* __restrict__ Q, const float* __restrict__ K,
            const float* __restrict__ V, float* __restrict__ O)
{
    extern __shared__ float sm[];
    float* Qs = sm;                  // [64][AS], Qs[d*AS + r]
    float* Ks = Qs + 64 * AS;        // [64][AS], Ks[d*AS + c]
    float* Vs = Ks + 64 * AS;        // [64][AS], Vs[key*AS + d]
    float* Ss = Vs + 64 * AS;        // [64][AS], Ss[r*AS + c]
    float* mrow  = Ss + 64 * AS;     // [64]
    float* lrow  = mrow + 64;        // [64]
    float* scrow = lrow + 64;        // [64]

    const int tid = threadIdx.x;
    const int qt = blockIdx.x;           // 0..31
    const int bh = blockIdx.y;           // 0..31
    const int b = bh >> 4;
    const int h = bh & 15;
    const int q0 = qt * 64;

    const float* Qg = Q + (size_t)b * SEQ * EMB + h * HDIM;
    const float* Kg = K + (size_t)b * SEQ * EMB + h * HDIM;
    const float* Vg = V + (size_t)b * SEQ * EMB + h * HDIM;

    const int dd = tid & 63;
    const int rb = tid >> 6;   // 0..3

    // Load Q tile transposed: Qs[d][r]
#pragma unroll
    for (int r = rb; r < 64; r += 4)
        Qs[dd * AS + r] = Qg[(size_t)(q0 + r) * EMB + dd];

    if (tid < 64) { mrow[tid] = -1e30f; lrow[tid] = 0.f; }

    const int tx = tid & 15;   // key/dim col group (4 cols)
    const int ty = tid >> 4;   // query row group (4 rows)

    float acc[4][4];
#pragma unroll
    for (int i = 0; i < 4; ++i)
#pragma unroll
        for (int j = 0; j < 4; ++j) acc[i][j] = 0.f;

    for (int kt = 0; kt < SEQ / 64; ++kt) {
        const int k0 = kt * 64;
        __syncthreads();  // previous iter done with Ks/Vs/Ss; also covers init

        // K tile transposed: Ks[d][c]
#pragma unroll
        for (int r = rb; r < 64; r += 4)
            Ks[dd * AS + r] = Kg[(size_t)(k0 + r) * EMB + dd];

        // V tile natural: Vs[key][d]
        {
            int vr = tid >> 4;
            int vc = (tid & 15) * 4;
#pragma unroll
            for (int p = 0; p < 4; ++p) {
                float4 v = *(const float4*)&Vg[(size_t)(k0 + vr + p * 16) * EMB + vc];
                *(float4*)&Vs[(vr + p * 16) * AS + vc] = v;
            }
        }
        __syncthreads();

        // scores: sreg[i][j] = sum_d Q[r][d] * K[c][d]
        float sreg[4][4];
#pragma unroll
        for (int i = 0; i < 4; ++i)
#pragma unroll
            for (int j = 0; j < 4; ++j) sreg[i][j] = 0.f;

#pragma unroll
        for (int d = 0; d < 64; ++d) {
            float4 a = *(const float4*)&Qs[d * AS + ty * 4];
            float4 bb = *(const float4*)&Ks[d * AS + tx * 4];
            float av[4] = {a.x, a.y, a.z, a.w};
            float bv[4] = {bb.x, bb.y, bb.z, bb.w};
#pragma unroll
            for (int i = 0; i < 4; ++i)
#pragma unroll
                for (int j = 0; j < 4; ++j)
                    sreg[i][j] = fmaf(av[i], bv[j], sreg[i][j]);
        }

        // write scaled scores
#pragma unroll
        for (int i = 0; i < 4; ++i) {
            float4 o;
            o.x = sreg[i][0] * 0.125f;
            o.y = sreg[i][1] * 0.125f;
            o.z = sreg[i][2] * 0.125f;
            o.w = sreg[i][3] * 0.125f;
            *(float4*)&Ss[(ty * 4 + i) * AS + tx * 4] = o;
        }
        __syncthreads();

        // online softmax per row (64 worker threads)
        if (tid < 64) {
            const int r = tid;
            float mo = mrow[r];
            float mx = mo;
#pragma unroll
            for (int c = 0; c < 64; ++c) mx = fmaxf(mx, Ss[r * AS + c]);
            float sum = 0.f;
#pragma unroll
            for (int c = 0; c < 64; ++c) {
                float p = __expf(Ss[r * AS + c] - mx);
                Ss[r * AS + c] = p;
                sum += p;
            }
            float sc = __expf(mo - mx);
            scrow[r] = sc;
            lrow[r] = lrow[r] * sc + sum;
            mrow[r] = mx;
        }
        __syncthreads();

        // rescale accumulators
#pragma unroll
        for (int i = 0; i < 4; ++i) {
            float s = scrow[ty * 4 + i];
#pragma unroll
            for (int j = 0; j < 4; ++j) acc[i][j] *= s;
        }

        // acc += P @ V
#pragma unroll
        for (int kk = 0; kk < 64; ++kk) {
            float4 v = *(const float4*)&Vs[kk * AS + tx * 4];
            float vv[4] = {v.x, v.y, v.z, v.w};
#pragma unroll
            for (int i = 0; i < 4; ++i) {
                float p = Ss[(ty * 4 + i) * AS + kk];
#pragma unroll
                for (int j = 0; j < 4; ++j)
                    acc[i][j] = fmaf(p, vv[j], acc[i][j]);
            }
        }
    }

    __syncthreads();
    // epilogue: normalize and store ctx[b, q0+r, h, d]
#pragma unroll
    for (int i = 0; i < 4; ++i) {
        float inv = 1.f / lrow[ty * 4 + i];
        float4 o;
        o.x = acc[i][0] * inv;
        o.y = acc[i][1] * inv;
        o.z = acc[i][2] * inv;
        o.w = acc[i][3] * inv;
        size_t row = (size_t)b * SEQ + q0 + ty * 4 + i;
        *(float4*)&O[row * EMB + h * HDIM + tx * 4] = o;
    }
}

// ============================================================================
// launch
// ============================================================================
extern "C" void kernel_launch(void* const* d_in, const int* in_sizes, int n_in,
                              void* d_out, int out_size)
{
    const float* xv = (const float*)d_in[0];
    const float* xk = (const float*)d_in[1];
    const float* xq = (const float*)d_in[2];
    const float* Wq = (const float*)d_in[3];
    const float* bq = (const float*)d_in[4];
    const float* Wk = (const float*)d_in[5];
    const float* bk = (const float*)d_in[6];
    const float* Wv = (const float*)d_in[7];
    const float* bv = (const float*)d_in[8];
    const float* Wo = (const float*)d_in[9];
    const float* bo = (const float*)d_in[10];
    float* out = (float*)d_out;

    float *Qd, *Kd, *Vd, *Cd;
    cudaGetSymbolAddress((void**)&Qd, g_Q);
    cudaGetSymbolAddress((void**)&Kd, g_K);
    cudaGetSymbolAddress((void**)&Vd, g_V);
    cudaGetSymbolAddress((void**)&Cd, g_C);

    dim3 ggrid(EMB / BN, MROWS / BM);   // (8, 32)
    dim3 gblk(256);

    gemm_bias_kernel<<<ggrid, gblk>>>(xq, Wq, bq, Qd, MROWS, EMB, EMB);
    gemm_bias_kernel<<<ggrid, gblk>>>(xk, Wk, bk, Kd, MROWS, EMB, EMB);
    gemm_bias_kernel<<<ggrid, gblk>>>(xv, Wv, bv, Vd, MROWS, EMB, EMB);

    size_t smem = (size_t)(4 * 64 * AS + 3 * 64) * sizeof(float);  // ~70 KB
    static int attr_set = 0;
    cudaFuncSetAttribute(attn_kernel, cudaFuncAttributeMaxDynamicSharedMemorySize,
                         (int)smem);
    (void)attr_set;

    dim3 agrid(SEQ / 64, BATCH * HEADS);  // (32, 32)
    attn_kernel<<<agrid, 256, smem>>>(Qd, Kd, Vd, Cd);

    gemm_bias_kernel<<<ggrid, gblk>>>(Cd, Wo, bo, out, MROWS, EMB, EMB);
}

// round 3
// speedup vs baseline: 1.3653x; 1.3653x over previous
#include <cuda_runtime.h>
#include <cuda_bf16.h>
#include <cstdint>
#include <math.h>

// Problem constants
#define BATCH 2
#define SEQ   2048
#define EMB   1024
#define HEADS 16
#define HDIM  64
#define MROWS (BATCH * SEQ)   // 4096

// ---------------- scratch (device globals; no allocations allowed) ---------
__device__ float g_Q[MROWS * EMB];
__device__ float g_K[MROWS * EMB];
__device__ float g_V[MROWS * EMB];
__device__ float g_C[MROWS * EMB];
__device__ float g_WT[4][EMB * EMB];   // transposed (and tf32-rounded) weights

// ============================================================================
// helpers
// ============================================================================
__device__ __forceinline__ uint32_t smem_u32(const void* p) {
    uint32_t a;
    asm("{ .reg .u64 t; cvta.to.shared.u64 t, %1; cvt.u32.u64 %0, t; }"
        : "=r"(a) : "l"(p));
    return a;
}

__device__ __forceinline__ uint32_t f32_to_tf32(float f) {
    uint32_t r;
    asm("cvt.rna.tf32.f32 %0, %1;" : "=r"(r) : "f"(f));
    return r;
}

#define MMA_TF32(c, a, b)                                                     \
    asm volatile("mma.sync.aligned.m16n8k8.row.col.f32.tf32.tf32.f32 "        \
                 "{%0,%1,%2,%3}, {%4,%5,%6,%7}, {%8,%9}, {%0,%1,%2,%3};"      \
                 : "+f"((c)[0]), "+f"((c)[1]), "+f"((c)[2]), "+f"((c)[3])     \
                 : "r"((a)[0]), "r"((a)[1]), "r"((a)[2]), "r"((a)[3]),        \
                   "r"((b)[0]), "r"((b)[1]))

#define LDS_V2(r0, r1, addr)                                                  \
    asm volatile("ld.shared.v2.b32 {%0,%1}, [%2];"                            \
                 : "=r"(r0), "=r"(r1) : "r"(addr))

// ============================================================================
// Weight transpose + tf32 rounding: WT[n][k] = rna_tf32(W[k][n])
// ============================================================================
__global__ void __launch_bounds__(256)
transpose_rna_kernel(const float* __restrict__ W, float* __restrict__ WT)
{
    __shared__ float tile[32][33];
    int x = blockIdx.x * 32 + threadIdx.x;   // col n
    int y = blockIdx.y * 32 + threadIdx.y;   // row k
#pragma unroll
    for (int j = 0; j < 32; j += 8)
        tile[threadIdx.y + j][threadIdx.x] = W[(size_t)(y + j) * EMB + x];
    __syncthreads();
    int xo = blockIdx.y * 32 + threadIdx.x;  // k
    int yo = blockIdx.x * 32 + threadIdx.y;  // n
#pragma unroll
    for (int j = 0; j < 32; j += 8) {
        uint32_t v = f32_to_tf32(tile[threadIdx.x][threadIdx.y + j]);
        WT[(size_t)(yo + j) * EMB + xo] = __uint_as_float(v);
    }
}

// ============================================================================
// tf32 mma.sync GEMM: C[M,N] = A[M,K] @ WT[N,K]^T + bias
// CTA tile 128x128, BK=32, 8 warps (2M x 4N), warp tile 64x32.
// Smem rows hold K=32 values permuted so that cols (t, t+4) are adjacent:
//   k -> pos = (k/8)*8 + (k%4)*2 + ((k%8)/4)
// Row stride 40 floats -> conflict-free ld.shared.v2 fragment loads.
// ============================================================================
#define GBM 128
#define GBN 128
#define GBK 32
#define RSTR 40                       // floats per smem row
#define TILE_F (128 * RSTR)           // floats per tile buffer
#define GSMEM_TOTAL (4 * TILE_F * 4)  // 2 bufs x (A,B) x 128x40 x 4B = 80 KB

__global__ void __launch_bounds__(256, 1)
gemm_tf32_kernel(const float* __restrict__ A, const float* __restrict__ WT,
                 const float* __restrict__ bias, float* __restrict__ C)
{
    extern __shared__ float smf[];
    const uint32_t sb = smem_u32(smf);

    const int tid = threadIdx.x;
    const int bn = blockIdx.x * GBN;
    const int bm = blockIdx.y * GBM;

    const int w    = tid >> 5;
    const int wm   = w & 1;         // 0..1
    const int wn   = w >> 1;        // 0..3
    const int lane = tid & 31;
    const int g    = lane >> 2;     // 0..7
    const int t    = lane & 3;      // 0..3

    // staging-load indices
    const int s  = tid & 7;         // k-quad: k = s*4
    const int r0 = tid >> 3;        // 0..31 (rows r0 + 32p)

    // smem buffers (float offsets)
    float* As[2] = { smf,                smf + TILE_F     };
    float* Bs[2] = { smf + 2 * TILE_F,   smf + 3 * TILE_F };
    const uint32_t AsU[2] = { sb,                       sb + TILE_F * 4 };
    const uint32_t BsU[2] = { sb + 2 * TILE_F * 4,      sb + 3 * TILE_F * 4 };

    const float* Ap = A  + (size_t)bm * EMB;
    const float* Bp = WT + (size_t)bn * EMB;

    float c[4][4][4];
#pragma unroll
    for (int mi = 0; mi < 4; ++mi)
#pragma unroll
        for (int ni = 0; ni < 4; ++ni)
#pragma unroll
            for (int j = 0; j < 4; ++j) c[mi][ni][j] = 0.f;

    // permuted STS base within a row: pos = (s>>1)*8 + (s&1), stride 2 for j
    const int pbase = (s >> 1) * 8 + (s & 1);

    float4 ar[4], br[4];

    // ---- prologue: load tile 0 ----
#pragma unroll
    for (int p = 0; p < 4; ++p) {
        ar[p] = *(const float4*)&Ap[(size_t)(r0 + 32 * p) * EMB + s * 4];
        br[p] = *(const float4*)&Bp[(size_t)(r0 + 32 * p) * EMB + s * 4];
    }
#pragma unroll
    for (int p = 0; p < 4; ++p) {
        float* da = As[0] + (r0 + 32 * p) * RSTR + pbase;
        float* db = Bs[0] + (r0 + 32 * p) * RSTR + pbase;
        da[0] = __uint_as_float(f32_to_tf32(ar[p].x));
        da[2] = __uint_as_float(f32_to_tf32(ar[p].y));
        da[4] = __uint_as_float(f32_to_tf32(ar[p].z));
        da[6] = __uint_as_float(f32_to_tf32(ar[p].w));
        db[0] = __uint_as_float(f32_to_tf32(br[p].x));
        db[2] = __uint_as_float(f32_to_tf32(br[p].y));
        db[4] = __uint_as_float(f32_to_tf32(br[p].z));
        db[6] = __uint_as_float(f32_to_tf32(br[p].w));
    }
    __syncthreads();

    const int NKT = EMB / GBK;   // 32
    for (int kt = 0; kt < NKT; ++kt) {
        const int b = kt & 1;

        // prefetch next tile into regs
        if (kt + 1 < NKT) {
            const int k0 = (kt + 1) * GBK;
#pragma unroll
            for (int p = 0; p < 4; ++p) {
                ar[p] = *(const float4*)&Ap[(size_t)(r0 + 32 * p) * EMB + k0 + s * 4];
                br[p] = *(const float4*)&Bp[(size_t)(r0 + 32 * p) * EMB + k0 + s * 4];
            }
        }

        // compute on buffer b
        const uint32_t aU = AsU[b];
        const uint32_t bU = BsU[b];
#pragma unroll
        for (int ks = 0; ks < 4; ++ks) {
            uint32_t af[4][4], bf[4][2];
#pragma unroll
            for (int mi = 0; mi < 4; ++mi) {
                uint32_t addr0 = aU + (uint32_t)(((wm * 64 + mi * 16 + g) * RSTR
                                                 + ks * 8 + 2 * t) * 4);
                LDS_V2(af[mi][0], af[mi][2], addr0);
                LDS_V2(af[mi][1], af[mi][3], addr0 + 8 * RSTR * 4);
            }
#pragma unroll
            for (int ni = 0; ni < 4; ++ni) {
                uint32_t addr = bU + (uint32_t)(((wn * 32 + ni * 8 + g) * RSTR
                                                + ks * 8 + 2 * t) * 4);
                LDS_V2(bf[ni][0], bf[ni][1], addr);
            }
#pragma unroll
            for (int mi = 0; mi < 4; ++mi)
#pragma unroll
                for (int ni = 0; ni < 4; ++ni)
                    MMA_TF32(c[mi][ni], af[mi], bf[ni]);
        }

        __syncthreads();

        if (kt + 1 < NKT) {
            const int nb = b ^ 1;
#pragma unroll
            for (int p = 0; p < 4; ++p) {
                float* da = As[nb] + (r0 + 32 * p) * RSTR + pbase;
                float* db = Bs[nb] + (r0 + 32 * p) * RSTR + pbase;
                da[0] = __uint_as_float(f32_to_tf32(ar[p].x));
                da[2] = __uint_as_float(f32_to_tf32(ar[p].y));
                da[4] = __uint_as_float(f32_to_tf32(ar[p].z));
                da[6] = __uint_as_float(f32_to_tf32(ar[p].w));
                db[0] = __uint_as_float(f32_to_tf32(br[p].x));
                db[2] = __uint_as_float(f32_to_tf32(br[p].y));
                db[4] = __uint_as_float(f32_to_tf32(br[p].z));
                db[6] = __uint_as_float(f32_to_tf32(br[p].w));
            }
            __syncthreads();
        }
    }

    // ---- epilogue: add bias, store ----
    const int colb = bn + wn * 32;
    float2 bj[4];
#pragma unroll
    for (int ni = 0; ni < 4; ++ni) {
        bj[ni].x = bias[colb + ni * 8 + 2 * t];
        bj[ni].y = bias[colb + ni * 8 + 2 * t + 1];
    }
#pragma unroll
    for (int mi = 0; mi < 4; ++mi) {
        const size_t row0 = (size_t)(bm + wm * 64 + mi * 16 + g);
        const size_t row1 = row0 + 8;
#pragma unroll
        for (int ni = 0; ni < 4; ++ni) {
            const int col = colb + ni * 8 + 2 * t;
            float2 o0, o1;
            o0.x = c[mi][ni][0] + bj[ni].x;
            o0.y = c[mi][ni][1] + bj[ni].y;
            o1.x = c[mi][ni][2] + bj[ni].x;
            o1.y = c[mi][ni][3] + bj[ni].y;
            *(float2*)&C[row0 * EMB + col] = o0;
            *(float2*)&C[row1 * EMB + col] = o1;
        }
    }
}

// ============================================================================
// Flash attention (unchanged, fp32): 64x64 tiles, online softmax.
// ============================================================================
#define AS 68   // smem stride

__global__ void __launch_bounds__(256)
attn_kernel(const float* __restrict__ Q, const float* __restrict__ K,
            const float* __restrict__ V, float* __restrict__ O)
{
    extern __shared__ float sm[];
    float* Qs = sm;                  // [64][AS], Qs[d*AS + r]
    float* Ks = Qs + 64 * AS;        // [64][AS], Ks[d*AS + c]
    float* Vs = Ks + 64 * AS;        // [64][AS], Vs[key*AS + d]
    float* Ss = Vs + 64 * AS;        // [64][AS], Ss[r*AS + c]
    float* mrow  = Ss + 64 * AS;     // [64]
    float* lrow  = mrow + 64;        // [64]
    float* scrow = lrow + 64;        // [64]

    const int tid = threadIdx.x;
    const int qt = blockIdx.x;
    const int bh = blockIdx.y;
    const int b = bh >> 4;
    const int h = bh & 15;
    const int q0 = qt * 64;

    const float* Qg = Q + (size_t)b * SEQ * EMB + h * HDIM;
    const float* Kg = K + (size_t)b * SEQ * EMB + h * HDIM;
    const float* Vg = V + (size_t)b * SEQ * EMB + h * HDIM;

    const int dd = tid & 63;
    const int rb = tid >> 6;

#pragma unroll
    for (int r = rb; r < 64; r += 4)
        Qs[dd * AS + r] = Qg[(size_t)(q0 + r) * EMB + dd];

    if (tid < 64) { mrow[tid] = -1e30f; lrow[tid] = 0.f; }

    const int tx = tid & 15;
    const int ty = tid >> 4;

    float acc[4][4];
#pragma unroll
    for (int i = 0; i < 4; ++i)
#pragma unroll
        for (int j = 0; j < 4; ++j) acc[i][j] = 0.f;

    for (int kt = 0; kt < SEQ / 64; ++kt) {
        const int k0 = kt * 64;
        __syncthreads();

#pragma unroll
        for (int r = rb; r < 64; r += 4)
            Ks[dd * AS + r] = Kg[(size_t)(k0 + r) * EMB + dd];

        {
            int vr = tid >> 4;
            int vc = (tid & 15) * 4;
#pragma unroll
            for (int p = 0; p < 4; ++p) {
                float4 v = *(const float4*)&Vg[(size_t)(k0 + vr + p * 16) * EMB + vc];
                *(float4*)&Vs[(vr + p * 16) * AS + vc] = v;
            }
        }
        __syncthreads();

        float sreg[4][4];
#pragma unroll
        for (int i = 0; i < 4; ++i)
#pragma unroll
            for (int j = 0; j < 4; ++j) sreg[i][j] = 0.f;

#pragma unroll
        for (int d = 0; d < 64; ++d) {
            float4 a = *(const float4*)&Qs[d * AS + ty * 4];
            float4 bb = *(const float4*)&Ks[d * AS + tx * 4];
            float av[4] = {a.x, a.y, a.z, a.w};
            float bv[4] = {bb.x, bb.y, bb.z, bb.w};
#pragma unroll
            for (int i = 0; i < 4; ++i)
#pragma unroll
                for (int j = 0; j < 4; ++j)
                    sreg[i][j] = fmaf(av[i], bv[j], sreg[i][j]);
        }

#pragma unroll
        for (int i = 0; i < 4; ++i) {
            float4 o;
            o.x = sreg[i][0] * 0.125f;
            o.y = sreg[i][1] * 0.125f;
            o.z = sreg[i][2] * 0.125f;
            o.w = sreg[i][3] * 0.125f;
            *(float4*)&Ss[(ty * 4 + i) * AS + tx * 4] = o;
        }
        __syncthreads();

        if (tid < 64) {
            const int r = tid;
            float mo = mrow[r];
            float mx = mo;
#pragma unroll
            for (int cc = 0; cc < 64; ++cc) mx = fmaxf(mx, Ss[r * AS + cc]);
            float sum = 0.f;
#pragma unroll
            for (int cc = 0; cc < 64; ++cc) {
                float p = __expf(Ss[r * AS + cc] - mx);
                Ss[r * AS + cc] = p;
                sum += p;
            }
            float sc = __expf(mo - mx);
            scrow[r] = sc;
            lrow[r] = lrow[r] * sc + sum;
            mrow[r] = mx;
        }
        __syncthreads();

#pragma unroll
        for (int i = 0; i < 4; ++i) {
            float s = scrow[ty * 4 + i];
#pragma unroll
            for (int j = 0; j < 4; ++j) acc[i][j] *= s;
        }

#pragma unroll
        for (int kk = 0; kk < 64; ++kk) {
            float4 v = *(const float4*)&Vs[kk * AS + tx * 4];
            float vv[4] = {v.x, v.y, v.z, v.w};
#pragma unroll
            for (int i = 0; i < 4; ++i) {
                float p = Ss[(ty * 4 + i) * AS + kk];
#pragma unroll
                for (int j = 0; j < 4; ++j)
                    acc[i][j] = fmaf(p, vv[j], acc[i][j]);
            }
        }
    }

    __syncthreads();
#pragma unroll
    for (int i = 0; i < 4; ++i) {
        float inv = 1.f / lrow[ty * 4 + i];
        float4 o;
        o.x = acc[i][0] * inv;
        o.y = acc[i][1] * inv;
        o.z = acc[i][2] * inv;
        o.w = acc[i][3] * inv;
        size_t row = (size_t)b * SEQ + q0 + ty * 4 + i;
        *(float4*)&O[row * EMB + h * HDIM + tx * 4] = o;
    }
}

// ============================================================================
// launch
// ============================================================================
extern "C" void kernel_launch(void* const* d_in, const int* in_sizes, int n_in,
                              void* d_out, int out_size)
{
    const float* xv = (const float*)d_in[0];
    const float* xk = (const float*)d_in[1];
    const float* xq = (const float*)d_in[2];
    const float* Wq = (const float*)d_in[3];
    const float* bq = (const float*)d_in[4];
    const float* Wk = (const float*)d_in[5];
    const float* bk = (const float*)d_in[6];
    const float* Wv = (const float*)d_in[7];
    const float* bv = (const float*)d_in[8];
    const float* Wo = (const float*)d_in[9];
    const float* bo = (const float*)d_in[10];
    float* out = (float*)d_out;

    float *Qd, *Kd, *Vd, *Cd, *WTd;
    cudaGetSymbolAddress((void**)&Qd, g_Q);
    cudaGetSymbolAddress((void**)&Kd, g_K);
    cudaGetSymbolAddress((void**)&Vd, g_V);
    cudaGetSymbolAddress((void**)&Cd, g_C);
    cudaGetSymbolAddress((void**)&WTd, g_WT);

    float* WqT = WTd + 0ll * EMB * EMB;
    float* WkT = WTd + 1ll * EMB * EMB;
    float* WvT = WTd + 2ll * EMB * EMB;
    float* WoT = WTd + 3ll * EMB * EMB;

    dim3 tgrid(EMB / 32, EMB / 32);
    dim3 tblk(32, 8);
    transpose_rna_kernel<<<tgrid, tblk>>>(Wq, WqT);
    transpose_rna_kernel<<<tgrid, tblk>>>(Wk, WkT);
    transpose_rna_kernel<<<tgrid, tblk>>>(Wv, WvT);
    transpose_rna_kernel<<<tgrid, tblk>>>(Wo, WoT);

    cudaFuncSetAttribute(gemm_tf32_kernel,
                         cudaFuncAttributeMaxDynamicSharedMemorySize, GSMEM_TOTAL);

    dim3 ggrid(EMB / GBN, MROWS / GBM);   // (8, 32)
    gemm_tf32_kernel<<<ggrid, 256, GSMEM_TOTAL>>>(xq, WqT, bq, Qd);
    gemm_tf32_kernel<<<ggrid, 256, GSMEM_TOTAL>>>(xk, WkT, bk, Kd);
    gemm_tf32_kernel<<<ggrid, 256, GSMEM_TOTAL>>>(xv, WvT, bv, Vd);

    size_t smem = (size_t)(4 * 64 * AS + 3 * 64) * sizeof(float);  // ~70 KB
    cudaFuncSetAttribute(attn_kernel, cudaFuncAttributeMaxDynamicSharedMemorySize,
                         (int)smem);
    dim3 agrid(SEQ / 64, BATCH * HEADS);  // (32, 32)
    attn_kernel<<<agrid, 256, smem>>>(Qd, Kd, Vd, Cd);

    gemm_tf32_kernel<<<ggrid, 256, GSMEM_TOTAL>>>(Cd, WoT, bo, out);
}

// round 4
// speedup vs baseline: 2.1069x; 1.5432x over previous
#include <cuda_runtime.h>
#include <cuda_bf16.h>
#include <cstdint>
#include <math.h>

// Problem constants
#define BATCH 2
#define SEQ   2048
#define EMB   1024
#define HEADS 16
#define HDIM  64
#define MROWS (BATCH * SEQ)   // 4096

// ---------------- scratch (device globals; no allocations allowed) ---------
__device__ float g_Q[MROWS * EMB];
__device__ float g_K[MROWS * EMB];
__device__ float g_V[MROWS * EMB];
__device__ float g_C[MROWS * EMB];
__device__ float g_WT[4][EMB * EMB];   // transposed (and tf32-rounded) weights

// ============================================================================
// helpers
// ============================================================================
__device__ __forceinline__ uint32_t smem_u32(const void* p) {
    uint32_t a;
    asm("{ .reg .u64 t; cvta.to.shared.u64 t, %1; cvt.u32.u64 %0, t; }"
        : "=r"(a) : "l"(p));
    return a;
}

__device__ __forceinline__ uint32_t f32_to_tf32(float f) {
    uint32_t r;
    asm("cvt.rna.tf32.f32 %0, %1;" : "=r"(r) : "f"(f));
    return r;
}

#define MMA_TF32(c, a, b)                                                     \
    asm volatile("mma.sync.aligned.m16n8k8.row.col.f32.tf32.tf32.f32 "        \
                 "{%0,%1,%2,%3}, {%4,%5,%6,%7}, {%8,%9}, {%0,%1,%2,%3};"      \
                 : "+f"((c)[0]), "+f"((c)[1]), "+f"((c)[2]), "+f"((c)[3])     \
                 : "r"((a)[0]), "r"((a)[1]), "r"((a)[2]), "r"((a)[3]),        \
                   "r"((b)[0]), "r"((b)[1]))

#define MMA_TF32F(c, a, b)                                                    \
    asm volatile("mma.sync.aligned.m16n8k8.row.col.f32.tf32.tf32.f32 "        \
                 "{%0,%1,%2,%3}, {%4,%5,%6,%7}, {%8,%9}, {%0,%1,%2,%3};"      \
                 : "+f"((c)[0]), "+f"((c)[1]), "+f"((c)[2]), "+f"((c)[3])     \
                 : "r"((a)[0]), "r"((a)[1]), "r"((a)[2]), "r"((a)[3]),        \
                   "r"((b)[0]), "r"((b)[1]))

#define LDS_V2(r0, r1, addr)                                                  \
    asm volatile("ld.shared.v2.b32 {%0,%1}, [%2];"                            \
                 : "=r"(r0), "=r"(r1) : "r"(addr))

// k-permutation: k -> (k/8)*8 + (k%4)*2 + ((k%8)/4)
__device__ __forceinline__ int posf(int k) {
    return ((k >> 3) << 3) + ((k & 3) << 1) + ((k & 7) >> 2);
}

// ============================================================================
// Weight transpose + tf32 rounding: WT[n][k] = rna_tf32(W[k][n])
// ============================================================================
__global__ void __launch_bounds__(256)
transpose_rna_kernel(const float* __restrict__ W, float* __restrict__ WT)
{
    __shared__ float tile[32][33];
    int x = blockIdx.x * 32 + threadIdx.x;
    int y = blockIdx.y * 32 + threadIdx.y;
#pragma unroll
    for (int j = 0; j < 32; j += 8)
        tile[threadIdx.y + j][threadIdx.x] = W[(size_t)(y + j) * EMB + x];
    __syncthreads();
    int xo = blockIdx.y * 32 + threadIdx.x;
    int yo = blockIdx.x * 32 + threadIdx.y;
#pragma unroll
    for (int j = 0; j < 32; j += 8) {
        uint32_t v = f32_to_tf32(tile[threadIdx.x][threadIdx.y + j]);
        WT[(size_t)(yo + j) * EMB + xo] = __uint_as_float(v);
    }
}

// ============================================================================
// tf32 mma.sync GEMM (unchanged from R3): C = A @ WT^T + bias
// ============================================================================
#define GBM 128
#define GBN 128
#define GBK 32
#define RSTR 40
#define TILE_F (128 * RSTR)
#define GSMEM_TOTAL (4 * TILE_F * 4)

__global__ void __launch_bounds__(256, 1)
gemm_tf32_kernel(const float* __restrict__ A, const float* __restrict__ WT,
                 const float* __restrict__ bias, float* __restrict__ C)
{
    extern __shared__ float smf[];
    const uint32_t sb = smem_u32(smf);

    const int tid = threadIdx.x;
    const int bn = blockIdx.x * GBN;
    const int bm = blockIdx.y * GBM;

    const int w    = tid >> 5;
    const int wm   = w & 1;
    const int wn   = w >> 1;
    const int lane = tid & 31;
    const int g    = lane >> 2;
    const int t    = lane & 3;

    const int s  = tid & 7;
    const int r0 = tid >> 3;

    float* As[2] = { smf,                smf + TILE_F     };
    float* Bs[2] = { smf + 2 * TILE_F,   smf + 3 * TILE_F };
    const uint32_t AsU[2] = { sb,                  sb + TILE_F * 4 };
    const uint32_t BsU[2] = { sb + 2 * TILE_F * 4, sb + 3 * TILE_F * 4 };

    const float* Ap = A  + (size_t)bm * EMB;
    const float* Bp = WT + (size_t)bn * EMB;

    float c[4][4][4];
#pragma unroll
    for (int mi = 0; mi < 4; ++mi)
#pragma unroll
        for (int ni = 0; ni < 4; ++ni)
#pragma unroll
            for (int j = 0; j < 4; ++j) c[mi][ni][j] = 0.f;

    const int pbase = (s >> 1) * 8 + (s & 1);

    float4 ar[4], br[4];

#pragma unroll
    for (int p = 0; p < 4; ++p) {
        ar[p] = *(const float4*)&Ap[(size_t)(r0 + 32 * p) * EMB + s * 4];
        br[p] = *(const float4*)&Bp[(size_t)(r0 + 32 * p) * EMB + s * 4];
    }
#pragma unroll
    for (int p = 0; p < 4; ++p) {
        float* da = As[0] + (r0 + 32 * p) * RSTR + pbase;
        float* db = Bs[0] + (r0 + 32 * p) * RSTR + pbase;
        da[0] = __uint_as_float(f32_to_tf32(ar[p].x));
        da[2] = __uint_as_float(f32_to_tf32(ar[p].y));
        da[4] = __uint_as_float(f32_to_tf32(ar[p].z));
        da[6] = __uint_as_float(f32_to_tf32(ar[p].w));
        db[0] = __uint_as_float(f32_to_tf32(br[p].x));
        db[2] = __uint_as_float(f32_to_tf32(br[p].y));
        db[4] = __uint_as_float(f32_to_tf32(br[p].z));
        db[6] = __uint_as_float(f32_to_tf32(br[p].w));
    }
    __syncthreads();

    const int NKT = EMB / GBK;
    for (int kt = 0; kt < NKT; ++kt) {
        const int b = kt & 1;

        if (kt + 1 < NKT) {
            const int k0 = (kt + 1) * GBK;
#pragma unroll
            for (int p = 0; p < 4; ++p) {
                ar[p] = *(const float4*)&Ap[(size_t)(r0 + 32 * p) * EMB + k0 + s * 4];
                br[p] = *(const float4*)&Bp[(size_t)(r0 + 32 * p) * EMB + k0 + s * 4];
            }
        }

        const uint32_t aU = AsU[b];
        const uint32_t bU = BsU[b];
#pragma unroll
        for (int ks = 0; ks < 4; ++ks) {
            uint32_t af[4][4], bf[4][2];
#pragma unroll
            for (int mi = 0; mi < 4; ++mi) {
                uint32_t addr0 = aU + (uint32_t)(((wm * 64 + mi * 16 + g) * RSTR
                                                 + ks * 8 + 2 * t) * 4);
                LDS_V2(af[mi][0], af[mi][2], addr0);
                LDS_V2(af[mi][1], af[mi][3], addr0 + 8 * RSTR * 4);
            }
#pragma unroll
            for (int ni = 0; ni < 4; ++ni) {
                uint32_t addr = bU + (uint32_t)(((wn * 32 + ni * 8 + g) * RSTR
                                                + ks * 8 + 2 * t) * 4);
                LDS_V2(bf[ni][0], bf[ni][1], addr);
            }
#pragma unroll
            for (int mi = 0; mi < 4; ++mi)
#pragma unroll
                for (int ni = 0; ni < 4; ++ni)
                    MMA_TF32(c[mi][ni], af[mi], bf[ni]);
        }

        __syncthreads();

        if (kt + 1 < NKT) {
            const int nb = b ^ 1;
#pragma unroll
            for (int p = 0; p < 4; ++p) {
                float* da = As[nb] + (r0 + 32 * p) * RSTR + pbase;
                float* db = Bs[nb] + (r0 + 32 * p) * RSTR + pbase;
                da[0] = __uint_as_float(f32_to_tf32(ar[p].x));
                da[2] = __uint_as_float(f32_to_tf32(ar[p].y));
                da[4] = __uint_as_float(f32_to_tf32(ar[p].z));
                da[6] = __uint_as_float(f32_to_tf32(ar[p].w));
                db[0] = __uint_as_float(f32_to_tf32(br[p].x));
                db[2] = __uint_as_float(f32_to_tf32(br[p].y));
                db[4] = __uint_as_float(f32_to_tf32(br[p].z));
                db[6] = __uint_as_float(f32_to_tf32(br[p].w));
            }
            __syncthreads();
        }
    }

    const int colb = bn + wn * 32;
    float2 bj[4];
#pragma unroll
    for (int ni = 0; ni < 4; ++ni) {
        bj[ni].x = bias[colb + ni * 8 + 2 * t];
        bj[ni].y = bias[colb + ni * 8 + 2 * t + 1];
    }
#pragma unroll
    for (int mi = 0; mi < 4; ++mi) {
        const size_t row0 = (size_t)(bm + wm * 64 + mi * 16 + g);
        const size_t row1 = row0 + 8;
#pragma unroll
        for (int ni = 0; ni < 4; ++ni) {
            const int col = colb + ni * 8 + 2 * t;
            float2 o0, o1;
            o0.x = c[mi][ni][0] + bj[ni].x;
            o0.y = c[mi][ni][1] + bj[ni].y;
            o1.x = c[mi][ni][2] + bj[ni].x;
            o1.y = c[mi][ni][3] + bj[ni].y;
            *(float2*)&C[row0 * EMB + col] = o0;
            *(float2*)&C[row1 * EMB + col] = o1;
        }
    }
}

// ============================================================================
// Flash attention with tf32 mma.sync.
// Block: 128 queries x one (b,h). 8 warps: 4 M-warps x 2 N-warps.
// Key tiles of 64. Q scaled by 0.125*log2(e) -> softmax uses exp2.
// ============================================================================
#define ATT_RST 72
#define ATT_VST 66
#define OFF_Q 0
#define OFF_K (128 * ATT_RST)              // 9216
#define OFF_V (OFF_K + 64 * ATT_RST)       // 13824
#define OFF_P (OFF_V + 64 * ATT_VST)       // 18048
#define OFF_M (OFF_P + 128 * ATT_RST)      // 27264
#define OFF_L (OFF_M + 128)
#define OFF_SC (OFF_L + 128)
#define OFF_PMAX (OFF_SC + 128)            // [2][128]
#define OFF_PSUM (OFF_PMAX + 256)          // [2][128]
#define ATT_SMEM ((OFF_PSUM + 256) * 4)    // ~112.6 KB

#define QSCALE 0.18033688f   // 0.125 * log2(e)

__global__ void __launch_bounds__(256, 1)
attn_mma_kernel(const float* __restrict__ Q, const float* __restrict__ K,
                const float* __restrict__ V, float* __restrict__ O)
{
    extern __shared__ float smf[];
    const uint32_t sb = smem_u32(smf);

    float* Qs = smf + OFF_Q;
    float* Ks = smf + OFF_K;
    float* Vt = smf + OFF_V;
    float* Ps = smf + OFF_P;
    float* mrow = smf + OFF_M;
    float* lrow = smf + OFF_L;
    float* scrow = smf + OFF_SC;
    float* pmax = smf + OFF_PMAX;
    float* psum = smf + OFF_PSUM;

    const uint32_t QsU = sb + OFF_Q * 4;
    const uint32_t KsU = sb + OFF_K * 4;
    const uint32_t VtU = sb + OFF_V * 4;
    const uint32_t PsU = sb + OFF_P * 4;

    const int tid = threadIdx.x;
    const int qt = blockIdx.x;           // 0..15
    const int bh = blockIdx.y;           // 0..31
    const int b = bh >> 4;
    const int h = bh & 15;
    const int q0 = qt * 128;

    const float* Qg = Q + (size_t)b * SEQ * EMB + h * HDIM;
    const float* Kg = K + (size_t)b * SEQ * EMB + h * HDIM;
    const float* Vg = V + (size_t)b * SEQ * EMB + h * HDIM;

    const int w    = tid >> 5;
    const int wm   = w & 3;         // 0..3 : 32 query rows each
    const int wn   = w >> 2;        // 0..1 : 32 key cols each
    const int lane = tid & 31;
    const int g    = lane >> 2;
    const int t    = lane & 3;

    // staging indices (Q/K): 16 quads per row
    const int s16 = tid & 15;
    const int r16 = tid >> 4;       // 0..15
    const int pb16 = (s16 >> 1) * 8 + (s16 & 1);
    // V staging indices
    const int vd = tid & 63;
    const int vkg = tid >> 6;       // 0..3

    // ---- stage Q (scaled), K0, V0 ----
#pragma unroll
    for (int p = 0; p < 8; ++p) {
        int r = r16 + 16 * p;
        float4 v = *(const float4*)&Qg[(size_t)(q0 + r) * EMB + s16 * 4];
        float* d = Qs + r * ATT_RST + pb16;
        d[0] = __uint_as_float(f32_to_tf32(v.x * QSCALE));
        d[2] = __uint_as_float(f32_to_tf32(v.y * QSCALE));
        d[4] = __uint_as_float(f32_to_tf32(v.z * QSCALE));
        d[6] = __uint_as_float(f32_to_tf32(v.w * QSCALE));
    }
#pragma unroll
    for (int p = 0; p < 4; ++p) {
        int r = r16 + 16 * p;
        float4 v = *(const float4*)&Kg[(size_t)r * EMB + s16 * 4];
        float* d = Ks + r * ATT_RST + pb16;
        d[0] = __uint_as_float(f32_to_tf32(v.x));
        d[2] = __uint_as_float(f32_to_tf32(v.y));
        d[4] = __uint_as_float(f32_to_tf32(v.z));
        d[6] = __uint_as_float(f32_to_tf32(v.w));
    }
#pragma unroll
    for (int kk = 0; kk < 16; ++kk) {
        int key = vkg * 16 + kk;
        float v = Vg[(size_t)key * EMB + vd];
        Vt[vd * ATT_VST + posf(key)] = __uint_as_float(f32_to_tf32(v));
    }
    if (tid < 128) { mrow[tid] = -1e30f; lrow[tid] = 0.f; }
    __syncthreads();

    // O accumulators [2 mtiles][4 ntiles][4]
    float o[2][4][4];
#pragma unroll
    for (int mi = 0; mi < 2; ++mi)
#pragma unroll
        for (int ni = 0; ni < 4; ++ni)
#pragma unroll
            for (int j = 0; j < 4; ++j) o[mi][ni][j] = 0.f;

    const int NT = SEQ / 64;   // 32
    float kr[4][4];            // K prefetch (4 float4)
    float vr[16];              // V prefetch

    for (int kt = 0; kt < NT; ++kt) {
        // prefetch next K/V tile into regs
        if (kt + 1 < NT) {
            const int k0n = (kt + 1) * 64;
#pragma unroll
            for (int p = 0; p < 4; ++p) {
                const float4 v = *(const float4*)&Kg[(size_t)(k0n + r16 + 16 * p) * EMB + s16 * 4];
                kr[p][0] = v.x; kr[p][1] = v.y; kr[p][2] = v.z; kr[p][3] = v.w;
            }
#pragma unroll
            for (int kk = 0; kk < 16; ++kk)
                vr[kk] = Vg[(size_t)(k0n + vkg * 16 + kk) * EMB + vd];
        }

        // ---- S = Qs @ Ks^T  (warp tile 32x32) ----
        float s[2][4][4];
#pragma unroll
        for (int mi = 0; mi < 2; ++mi)
#pragma unroll
            for (int ni = 0; ni < 4; ++ni)
#pragma unroll
                for (int j = 0; j < 4; ++j) s[mi][ni][j] = 0.f;

#pragma unroll
        for (int ks = 0; ks < 8; ++ks) {
            uint32_t af[2][4], bf[4][2];
#pragma unroll
            for (int mi = 0; mi < 2; ++mi) {
                uint32_t a0 = QsU + (uint32_t)(((wm * 32 + mi * 16 + g) * ATT_RST
                                                + ks * 8 + 2 * t) * 4);
                LDS_V2(af[mi][0], af[mi][2], a0);
                LDS_V2(af[mi][1], af[mi][3], a0 + 8 * ATT_RST * 4);
            }
#pragma unroll
            for (int ni = 0; ni < 4; ++ni) {
                uint32_t a = KsU + (uint32_t)(((wn * 32 + ni * 8 + g) * ATT_RST
                                               + ks * 8 + 2 * t) * 4);
                LDS_V2(bf[ni][0], bf[ni][1], a);
            }
#pragma unroll
            for (int mi = 0; mi < 2; ++mi)
#pragma unroll
                for (int ni = 0; ni < 4; ++ni)
                    MMA_TF32(s[mi][ni], af[mi], bf[ni]);
        }

        // ---- partial row max (per thread 4 rows x 8 cols) ----
#pragma unroll
        for (int mi = 0; mi < 2; ++mi) {
#pragma unroll
            for (int hh = 0; hh < 2; ++hh) {
                float m = s[mi][0][2 * hh];
#pragma unroll
                for (int ni = 0; ni < 4; ++ni) {
                    m = fmaxf(m, s[mi][ni][2 * hh]);
                    m = fmaxf(m, s[mi][ni][2 * hh + 1]);
                }
                m = fmaxf(m, __shfl_xor_sync(0xffffffffu, m, 1));
                m = fmaxf(m, __shfl_xor_sync(0xffffffffu, m, 2));
                if (t == 0)
                    pmax[wn * 128 + wm * 32 + mi * 16 + hh * 8 + g] = m;
            }
        }
        __syncthreads();

        if (tid < 128) {
            float mo = mrow[tid];
            float mx = fmaxf(mo, fmaxf(pmax[tid], pmax[128 + tid]));
            mrow[tid] = mx;
            scrow[tid] = exp2f(mo - mx);
        }
        __syncthreads();

        // ---- exp, write P (tf32, permuted), partial sums, rescale O ----
        float mxv[2][2], scv[2][2];
#pragma unroll
        for (int mi = 0; mi < 2; ++mi)
#pragma unroll
            for (int hh = 0; hh < 2; ++hh) {
                int row = wm * 32 + mi * 16 + hh * 8 + g;
                mxv[mi][hh] = mrow[row];
                scv[mi][hh] = scrow[row];
            }

        const int pos0 = ((2 * t) & 3) * 2 + ((2 * t) >> 2);
        const int pos1 = ((2 * t + 1) & 3) * 2 + ((2 * t + 1) >> 2);

        float ls[2][2] = {{0.f, 0.f}, {0.f, 0.f}};
#pragma unroll
        for (int mi = 0; mi < 2; ++mi) {
#pragma unroll
            for (int hh = 0; hh < 2; ++hh) {
                const int row = wm * 32 + mi * 16 + hh * 8 + g;
                float* prow = Ps + row * ATT_RST;
#pragma unroll
                for (int ni = 0; ni < 4; ++ni) {
                    float p0 = exp2f(s[mi][ni][2 * hh]     - mxv[mi][hh]);
                    float p1 = exp2f(s[mi][ni][2 * hh + 1] - mxv[mi][hh]);
                    float p0r = __uint_as_float(f32_to_tf32(p0));
                    float p1r = __uint_as_float(f32_to_tf32(p1));
                    ls[mi][hh] += p0r + p1r;
                    const int kb = (wn * 4 + ni) * 8;
                    prow[kb + pos0] = p0r;
                    prow[kb + pos1] = p1r;
                }
#pragma unroll
                for (int ni = 0; ni < 4; ++ni) {
                    o[mi][ni][2 * hh]     *= scv[mi][hh];
                    o[mi][ni][2 * hh + 1] *= scv[mi][hh];
                }
            }
        }
#pragma unroll
        for (int mi = 0; mi < 2; ++mi)
#pragma unroll
            for (int hh = 0; hh < 2; ++hh) {
                float v = ls[mi][hh];
                v += __shfl_xor_sync(0xffffffffu, v, 1);
                v += __shfl_xor_sync(0xffffffffu, v, 2);
                if (t == 0)
                    psum[wn * 128 + wm * 32 + mi * 16 + hh * 8 + g] = v;
            }
        __syncthreads();

        if (tid < 128)
            lrow[tid] = lrow[tid] * scrow[tid] + psum[tid] + psum[128 + tid];

        // ---- O += P @ Vt ----
#pragma unroll
        for (int ks = 0; ks < 8; ++ks) {
            uint32_t af[2][4], bf[4][2];
#pragma unroll
            for (int mi = 0; mi < 2; ++mi) {
                uint32_t a0 = PsU + (uint32_t)(((wm * 32 + mi * 16 + g) * ATT_RST
                                                + ks * 8 + 2 * t) * 4);
                LDS_V2(af[mi][0], af[mi][2], a0);
                LDS_V2(af[mi][1], af[mi][3], a0 + 8 * ATT_RST * 4);
            }
#pragma unroll
            for (int ni = 0; ni < 4; ++ni) {
                uint32_t a = VtU + (uint32_t)(((wn * 32 + ni * 8 + g) * ATT_VST
                                               + ks * 8 + 2 * t) * 4);
                LDS_V2(bf[ni][0], bf[ni][1], a);
            }
#pragma unroll
            for (int mi = 0; mi < 2; ++mi)
#pragma unroll
                for (int ni = 0; ni < 4; ++ni)
                    MMA_TF32F(o[mi][ni], af[mi], bf[ni]);
        }
        __syncthreads();

        // ---- stage next K/V tiles from prefetch regs ----
        if (kt + 1 < NT) {
#pragma unroll
            for (int p = 0; p < 4; ++p) {
                float* d = Ks + (r16 + 16 * p) * ATT_RST + pb16;
                d[0] = __uint_as_float(f32_to_tf32(kr[p][0]));
                d[2] = __uint_as_float(f32_to_tf32(kr[p][1]));
                d[4] = __uint_as_float(f32_to_tf32(kr[p][2]));
                d[6] = __uint_as_float(f32_to_tf32(kr[p][3]));
            }
#pragma unroll
            for (int kk = 0; kk < 16; ++kk) {
                int key = vkg * 16 + kk;
                Vt[vd * ATT_VST + posf(key)] = __uint_as_float(f32_to_tf32(vr[kk]));
            }
            __syncthreads();
        }
    }

    // ---- epilogue: normalize, store ctx[b, q, h, d] ----
#pragma unroll
    for (int mi = 0; mi < 2; ++mi) {
#pragma unroll
        for (int hh = 0; hh < 2; ++hh) {
            const int row = wm * 32 + mi * 16 + hh * 8 + g;
            const float inv = 1.f / lrow[row];
            const size_t grow = (size_t)(b * SEQ + q0 + row) * EMB + h * HDIM;
#pragma unroll
            for (int ni = 0; ni < 4; ++ni) {
                float2 ov;
                ov.x = o[mi][ni][2 * hh]     * inv;
                ov.y = o[mi][ni][2 * hh + 1] * inv;
                *(float2*)&O[grow + wn * 32 + ni * 8 + 2 * t] = ov;
            }
        }
    }
}

// ============================================================================
// launch
// ============================================================================
extern "C" void kernel_launch(void* const* d_in, const int* in_sizes, int n_in,
                              void* d_out, int out_size)
{
    const float* xv = (const float*)d_in[0];
    const float* xk = (const float*)d_in[1];
    const float* xq = (const float*)d_in[2];
    const float* Wq = (const float*)d_in[3];
    const float* bq = (const float*)d_in[4];
    const float* Wk = (const float*)d_in[5];
    const float* bk = (const float*)d_in[6];
    const float* Wv = (const float*)d_in[7];
    const float* bv = (const float*)d_in[8];
    const float* Wo = (const float*)d_in[9];
    const float* bo = (const float*)d_in[10];
    float* out = (float*)d_out;

    float *Qd, *Kd, *Vd, *Cd, *WTd;
    cudaGetSymbolAddress((void**)&Qd, g_Q);
    cudaGetSymbolAddress((void**)&Kd, g_K);
    cudaGetSymbolAddress((void**)&Vd, g_V);
    cudaGetSymbolAddress((void**)&Cd, g_C);
    cudaGetSymbolAddress((void**)&WTd, g_WT);

    float* WqT = WTd + 0ll * EMB * EMB;
    float* WkT = WTd + 1ll * EMB * EMB;
    float* WvT = WTd + 2ll * EMB * EMB;
    float* WoT = WTd + 3ll * EMB * EMB;

    dim3 tgrid(EMB / 32, EMB / 32);
    dim3 tblk(32, 8);
    transpose_rna_kernel<<<tgrid, tblk>>>(Wq, WqT);
    transpose_rna_kernel<<<tgrid, tblk>>>(Wk, WkT);
    transpose_rna_kernel<<<tgrid, tblk>>>(Wv, WvT);
    transpose_rna_kernel<<<tgrid, tblk>>>(Wo, WoT);

    cudaFuncSetAttribute(gemm_tf32_kernel,
                         cudaFuncAttributeMaxDynamicSharedMemorySize, GSMEM_TOTAL);

    dim3 ggrid(EMB / GBN, MROWS / GBM);   // (8, 32)
    gemm_tf32_kernel<<<ggrid, 256, GSMEM_TOTAL>>>(xq, WqT, bq, Qd);
    gemm_tf32_kernel<<<ggrid, 256, GSMEM_TOTAL>>>(xk, WkT, bk, Kd);
    gemm_tf32_kernel<<<ggrid, 256, GSMEM_TOTAL>>>(xv, WvT, bv, Vd);

    cudaFuncSetAttribute(attn_mma_kernel,
                         cudaFuncAttributeMaxDynamicSharedMemorySize, ATT_SMEM);
    dim3 agrid(SEQ / 128, BATCH * HEADS);  // (16, 32)
    attn_mma_kernel<<<agrid, 256, ATT_SMEM>>>(Qd, Kd, Vd, Cd);

    gemm_tf32_kernel<<<ggrid, 256, GSMEM_TOTAL>>>(Cd, WoT, bo, out);
}